// round 1
// baseline (speedup 1.0000x reference)
#include <cuda_runtime.h>
#include <cstdint>

#define THREADS 256
#define BT 64

// Fused TensorTrain kernel, fp32 baseline.
// Grid: 256 CTAs, each handles 64 batch rows. Block: 256 threads (ty=tid/16, tx=tid%16).
// Thread (ty,tx) computes M-rows m=ty*4..ty*4+3, scan-matrix row i=tx (cols r=tx*16..tx*16+15).
__global__ __launch_bounds__(THREADS, 2)
void tt_fused_kernel(const float* __restrict__ nh,   // [16384][8][256]
                     const float* __restrict__ te,   // [16384][64]
                     const float* __restrict__ U,    // [8][4][256][272]
                     const float* __restrict__ bB,   // [8][4][1][272]
                     const float* __restrict__ Ut,   // [4][64][16]
                     const float* __restrict__ bt,   // [4][1][16]
                     const float* __restrict__ Uo,   // [4][16][256]
                     const float* __restrict__ bo,   // [4][1][256]
                     float* __restrict__ out)        // [16384][1024]
{
    extern __shared__ float smem[];
    float* sA = smem;                     // [64][256] nh channel tile
    float* sB = smem + 64 * 256;          // [16][256] U k-slice
    float* sX = smem + 64 * 256 + 16 * 256; // [64][64] type embs, then [64][4][16] carries

    const int tid = threadIdx.x;
    const int tx  = tid & 15;
    const int ty  = tid >> 4;
    const int b0  = blockIdx.x * BT;

    float4* sA4 = (float4*)sA;
    float4* sB4 = (float4*)sB;
    float4* sX4 = (float4*)sX;

    // ---- load type-embedding tile [64][64] ----
    #pragma unroll
    for (int i = 0; i < 4; i++) {
        int idx = tid + i * THREADS;            // float4 index 0..1023
        int m = idx >> 4, t4 = idx & 15;
        sX4[idx] = ((const float4*)(te + (size_t)(b0 + m) * 64))[t4];
    }
    __syncthreads();

    // ---- v0 = te @ U_type + b_type (into registers first; sX still holds te) ----
    float vc[4][4];
    #pragma unroll
    for (int a = 0; a < 4; a++) {
        float btv = __ldg(bt + a * 16 + tx);
        float s0 = btv, s1 = btv, s2 = btv, s3 = btv;
        const float* ut = Ut + a * 64 * 16 + tx;
        const float* x0 = sX + (ty * 4 + 0) * 64;
        const float* x1 = sX + (ty * 4 + 1) * 64;
        const float* x2 = sX + (ty * 4 + 2) * 64;
        const float* x3 = sX + (ty * 4 + 3) * 64;
        #pragma unroll 8
        for (int t = 0; t < 64; t++) {
            float u = __ldg(ut + t * 16);
            s0 += x0[t] * u; s1 += x1[t] * u; s2 += x2[t] * u; s3 += x3[t] * u;
        }
        vc[a][0] = s0; vc[a][1] = s1; vc[a][2] = s2; vc[a][3] = s3;
    }
    __syncthreads();  // all threads done reading te before sX becomes carry storage

    // ---- stash carries in sX as [m][a][16]; element [m][a][tx] is thread-private ----
    #pragma unroll
    for (int a = 0; a < 4; a++)
        #pragma unroll
        for (int mi = 0; mi < 4; mi++)
            sX[((ty * 4 + mi) * 4 + a) * 16 + tx] = vc[a][mi];
    // no sync needed: each slot is read/written only by the thread that owns it

    // ---- main loop over channels (sequential scan dependency) ----
    for (int c = 0; c < 8; c++) {
        __syncthreads();  // previous c's readers of sA are done
        // load nh[:, c, :] tile -> sA [64][256]
        #pragma unroll
        for (int i = 0; i < 16; i++) {
            int idx = tid + i * THREADS;        // float4 index 0..4095
            int m = idx >> 6, k4 = idx & 63;
            sA4[idx] = ((const float4*)(nh + ((size_t)(b0 + m) * 8 + c) * 256))[k4];
        }
        // sA readiness is guarded by the first __syncthreads in the kb loop below

        #pragma unroll 1
        for (int a = 0; a < 4; a++) {
            float acc[4][16];
            #pragma unroll
            for (int mi = 0; mi < 4; mi++)
                #pragma unroll
                for (int jj = 0; jj < 16; jj++) acc[mi][jj] = 0.f;

            const float* Uca = U + (size_t)(c * 4 + a) * 256 * 272;

            #pragma unroll 1
            for (int kb = 0; kb < 16; kb++) {
                __syncthreads();  // prior readers of sB done (also guards sA load at kb=0)
                #pragma unroll
                for (int i = 0; i < 4; i++) {
                    int idx = tid + i * THREADS;     // float4 index 0..1023
                    int kk = idx >> 6, r4 = idx & 63;
                    sB4[idx] = ((const float4*)(Uca + (size_t)(kb * 16 + kk) * 272))[r4];
                }
                __syncthreads();
                #pragma unroll
                for (int kk = 0; kk < 16; kk++) {
                    float4 bv0 = sB4[kk * 64 + tx * 4 + 0];
                    float4 bv1 = sB4[kk * 64 + tx * 4 + 1];
                    float4 bv2 = sB4[kk * 64 + tx * 4 + 2];
                    float4 bv3 = sB4[kk * 64 + tx * 4 + 3];
                    #pragma unroll
                    for (int mi = 0; mi < 4; mi++) {
                        float av = sA[(ty * 4 + mi) * 256 + kb * 16 + kk];
                        acc[mi][0]  += av * bv0.x;  acc[mi][1]  += av * bv0.y;
                        acc[mi][2]  += av * bv0.z;  acc[mi][3]  += av * bv0.w;
                        acc[mi][4]  += av * bv1.x;  acc[mi][5]  += av * bv1.y;
                        acc[mi][6]  += av * bv1.z;  acc[mi][7]  += av * bv1.w;
                        acc[mi][8]  += av * bv2.x;  acc[mi][9]  += av * bv2.y;
                        acc[mi][10] += av * bv2.z;  acc[mi][11] += av * bv2.w;
                        acc[mi][12] += av * bv3.x;  acc[mi][13] += av * bv3.y;
                        acc[mi][14] += av * bv3.z;  acc[mi][15] += av * bv3.w;
                    }
                }
            }

            // + ris bias b[c][a][0][r]  (same for all m)
            const float* bp = bB + (size_t)(c * 4 + a) * 272 + tx * 16;
            #pragma unroll
            for (int jj = 0; jj < 16; jj++) {
                float bb = __ldg(bp + jj);
                #pragma unroll
                for (int mi = 0; mi < 4; mi++) acc[mi][jj] += bb;
            }

            // scan update: v_new[j] = sum_i (v[i] + [i==15]) * M[i][j]
            // (b_rank == row 15 of U_rank in the reference — fold it into the coefficient)
            #pragma unroll
            for (int mi = 0; mi < 4; mi++) {
                float coef = sX[((ty * 4 + mi) * 4 + a) * 16 + tx]  // v[i=tx] for this (m,a)
                           + ((tx == 15) ? 1.0f : 0.0f);
                #pragma unroll
                for (int jj = 0; jj < 16; jj++) acc[mi][jj] *= coef;
            }
            // reduce over i across the 16-lane tx group (stays inside the warp)
            #pragma unroll
            for (int s = 1; s < 16; s <<= 1) {
                #pragma unroll
                for (int mi = 0; mi < 4; mi++)
                    #pragma unroll
                    for (int jj = 0; jj < 16; jj++)
                        acc[mi][jj] += __shfl_xor_sync(0xffffffffu, acc[mi][jj], s);
            }
            // lane tx keeps component j == tx as the new carry
            #pragma unroll
            for (int mi = 0; mi < 4; mi++) {
                float nv = 0.f;
                #pragma unroll
                for (int jj = 0; jj < 16; jj++) nv = (jj == tx) ? acc[mi][jj] : nv;
                sX[((ty * 4 + mi) * 4 + a) * 16 + tx] = nv;
            }
        }
    }

    __syncthreads();  // all carries final and visible

    // ---- output projection: out[m][a*256+hh] = v[m][a] . Uo[a][:,hh] + bo[a][hh] ----
    #pragma unroll 1
    for (int i = 0; i < 4; i++) {
        int q  = tid + i * THREADS;      // 0..1023
        int a  = q >> 8, hh = q & 255;
        float uo[16];
        #pragma unroll
        for (int r = 0; r < 16; r++) uo[r] = __ldg(Uo + (size_t)a * 4096 + r * 256 + hh);
        float bov = __ldg(bo + a * 256 + hh);
        #pragma unroll 4
        for (int m = 0; m < 64; m++) {
            const float4* vr4 = (const float4*)(sX + (m * 4 + a) * 16);
            float4 v0 = vr4[0], v1 = vr4[1], v2 = vr4[2], v3 = vr4[3];
            float s = bov;
            s += v0.x * uo[0]  + v0.y * uo[1]  + v0.z * uo[2]  + v0.w * uo[3];
            s += v1.x * uo[4]  + v1.y * uo[5]  + v1.z * uo[6]  + v1.w * uo[7];
            s += v2.x * uo[8]  + v2.y * uo[9]  + v2.z * uo[10] + v2.w * uo[11];
            s += v3.x * uo[12] + v3.y * uo[13] + v3.z * uo[14] + v3.w * uo[15];
            out[(size_t)(b0 + m) * 1024 + q] = s;
        }
    }
}

extern "C" void kernel_launch(void* const* d_in, const int* in_sizes, int n_in,
                              void* d_out, int out_size) {
    const float* nh = (const float*)d_in[0];
    const float* te = (const float*)d_in[1];
    const float* U  = (const float*)d_in[2];
    const float* bB = (const float*)d_in[3];
    const float* Ut = (const float*)d_in[4];
    const float* bt = (const float*)d_in[5];
    const float* Uo = (const float*)d_in[6];
    const float* bo = (const float*)d_in[7];
    float* out = (float*)d_out;

    const int smem_bytes = (64 * 256 + 16 * 256 + 64 * 64) * (int)sizeof(float); // 96 KB
    cudaFuncSetAttribute(tt_fused_kernel,
                         cudaFuncAttributeMaxDynamicSharedMemorySize, smem_bytes);
    tt_fused_kernel<<<256, THREADS, smem_bytes>>>(nh, te, U, bB, Ut, bt, Uo, bo, out);
}

// round 2
// speedup vs baseline: 1.8812x; 1.8812x over previous
#include <cuda_runtime.h>
#include <cstdint>

#define THREADS 256
#define BT 64

// sB slice loader: U[c][a] rows kb*16..kb*16+15, first 256 of 272 cols -> [16][256] floats
__device__ __forceinline__ void storeB(float4* dst4, const float* __restrict__ Uca,
                                       int kb, int tid) {
    #pragma unroll
    for (int i = 0; i < 4; i++) {
        int idx = tid + i * THREADS;          // float4 index 0..1023
        int kk = idx >> 6, r4 = idx & 63;
        dst4[idx] = ((const float4*)(Uca + (size_t)(kb * 16 + kk) * 272))[r4];
    }
}

// Grid: 256 CTAs x 64 batch rows. Block 256 threads: ty=tid/16 (4 m-rows each), tx=tid%16.
// Thread (ty,tx) computes ris columns r = i*16+tx for i=0..15 (scan-matrix column tx).
__global__ __launch_bounds__(THREADS, 2)
void tt_fused_kernel(const float* __restrict__ nh,   // [16384][8][256]
                     const float* __restrict__ te,   // [16384][64]
                     const float* __restrict__ U,    // [8][4][256][272]
                     const float* __restrict__ bB,   // [8][4][1][272]
                     const float* __restrict__ Ut,   // [4][64][16]
                     const float* __restrict__ bt,   // [4][1][16]
                     const float* __restrict__ Uo,   // [4][16][256]
                     const float* __restrict__ bo,   // [4][1][256]
                     float* __restrict__ out)        // [16384][1024]
{
    extern __shared__ float smem[];
    float* sA  = smem;                         // [64][256]  16384 f
    float* sB0 = smem + 16384;                 // [16][256]   4096 f
    float* sB1 = smem + 16384 + 4096;          // [16][256]   4096 f
    float* sX  = smem + 16384 + 8192;          // [64][64] te tile, later [64][4][16] carries

    const int tid = threadIdx.x;
    const int tx  = tid & 15;
    const int ty  = tid >> 4;
    const int b0  = blockIdx.x * BT;

    float4* sA4 = (float4*)sA;
    float4* sX4 = (float4*)sX;
    float*  sBb[2] = { sB0, sB1 };
    float4* sBb4[2] = { (float4*)sB0, (float4*)sB1 };

    // ---- load type-embedding tile [64][64] into sX ----
    #pragma unroll
    for (int i = 0; i < 4; i++) {
        int idx = tid + i * THREADS;           // float4 index 0..1023
        int m = idx >> 4, t4 = idx & 15;
        sX4[idx] = ((const float4*)(te + (size_t)(b0 + m) * 64))[t4];
    }
    __syncthreads();

    // ---- v0 = te @ U_type + b_type : carry component tx per (a, mi), in registers ----
    float vcar[4][4];
    #pragma unroll
    for (int a = 0; a < 4; a++) {
        float btv = __ldg(bt + a * 16 + tx);
        float s0 = btv, s1 = btv, s2 = btv, s3 = btv;
        const float* ut = Ut + a * 64 * 16 + tx;
        const float* x0 = sX + (ty * 4 + 0) * 64;
        const float* x1 = sX + (ty * 4 + 1) * 64;
        const float* x2 = sX + (ty * 4 + 2) * 64;
        const float* x3 = sX + (ty * 4 + 3) * 64;
        #pragma unroll 8
        for (int t = 0; t < 64; t++) {
            float u = __ldg(ut + t * 16);
            s0 += x0[t] * u; s1 += x1[t] * u; s2 += x2[t] * u; s3 += x3[t] * u;
        }
        vcar[a][0] = s0; vcar[a][1] = s1; vcar[a][2] = s2; vcar[a][3] = s3;
    }
    // sX stays as te until overwritten by carries at the end; no further reads of te.

    // ---- main loop: c outer (sequential scan), a middle, kb inner with double-buffered sB ----
    for (int c = 0; c < 8; c++) {
        __syncthreads();  // prev c readers of sA (and sB) done
        // load nh[:, c, :] -> sA
        #pragma unroll
        for (int i = 0; i < 16; i++) {
            int idx = tid + i * THREADS;       // float4 index 0..4095
            int m = idx >> 6, k4 = idx & 63;
            sA4[idx] = ((const float4*)(nh + ((size_t)(b0 + m) * 8 + c) * 256))[k4];
        }
        if (c == 0) storeB(sBb4[0], U, 0, tid);   // prime slice s=0

        #pragma unroll 1
        for (int a = 0; a < 4; a++) {
            float acc[4][16];
            #pragma unroll
            for (int mi = 0; mi < 4; mi++)
                #pragma unroll
                for (int i = 0; i < 16; i++) acc[mi][i] = 0.f;

            #pragma unroll 1
            for (int kb = 0; kb < 16; kb++) {
                const int s = ((c * 4 + a) << 4) | kb;   // linear slice id 0..511
                const int cur = kb & 1;
                __syncthreads();  // slice s visible in buf[cur]; buf[1-cur] free

                if (s + 1 < 512) {
                    const float* UcaN = U + (size_t)((s + 1) >> 4) * (256 * 272);
                    storeB(sBb4[(kb + 1) & 1], UcaN, (s + 1) & 15, tid);
                }

                const float* Bb = sBb[cur];
                #pragma unroll
                for (int kkg = 0; kkg < 4; kkg++) {
                    float4 av0 = sA4[(ty * 4 + 0) * 64 + kb * 4 + kkg];
                    float4 av1 = sA4[(ty * 4 + 1) * 64 + kb * 4 + kkg];
                    float4 av2 = sA4[(ty * 4 + 2) * 64 + kb * 4 + kkg];
                    float4 av3 = sA4[(ty * 4 + 3) * 64 + kb * 4 + kkg];
                    #pragma unroll
                    for (int kq = 0; kq < 4; kq++) {
                        const int kk = kkg * 4 + kq;
                        const float a0 = (kq == 0) ? av0.x : (kq == 1) ? av0.y : (kq == 2) ? av0.z : av0.w;
                        const float a1 = (kq == 0) ? av1.x : (kq == 1) ? av1.y : (kq == 2) ? av1.z : av1.w;
                        const float a2 = (kq == 0) ? av2.x : (kq == 1) ? av2.y : (kq == 2) ? av2.z : av2.w;
                        const float a3 = (kq == 0) ? av3.x : (kq == 1) ? av3.y : (kq == 2) ? av3.z : av3.w;
                        const float* br = Bb + kk * 256 + tx;
                        #pragma unroll
                        for (int i = 0; i < 16; i++) {
                            float u = br[i * 16];      // lanes consecutive: conflict-free
                            acc[0][i] += a0 * u;
                            acc[1][i] += a1 * u;
                            acc[2][i] += a2 * u;
                            acc[3][i] += a3 * u;
                        }
                    }
                }
            }

            // + bias b[c][a][0][r], r = i*16+tx
            const float* bp = bB + (size_t)(c * 4 + a) * 272 + tx;
            #pragma unroll
            for (int i = 0; i < 16; i++) {
                float bb = __ldg(bp + i * 16);
                #pragma unroll
                for (int mi = 0; mi < 4; mi++) acc[mi][i] += bb;
            }

            // scan: v_new[tx] = sum_i (v[i] + [i==15]) * M[i][tx]; M[i][tx] = acc[mi][i]
            #pragma unroll
            for (int mi = 0; mi < 4; mi++) {
                float nv = 0.f;
                #pragma unroll
                for (int i = 0; i < 16; i++) {
                    float coef = __shfl_sync(0xffffffffu, vcar[a][mi], i, 16);
                    if (i == 15) coef += 1.0f;
                    nv += coef * acc[mi][i];
                }
                vcar[a][mi] = nv;
            }
        }
    }

    // ---- dump carries to sX as [m][a][16] ----
    __syncthreads();  // done with te contents / prior sB readers
    #pragma unroll
    for (int a = 0; a < 4; a++)
        #pragma unroll
        for (int mi = 0; mi < 4; mi++)
            sX[((ty * 4 + mi) * 4 + a) * 16 + tx] = vcar[a][mi];
    __syncthreads();

    // ---- output projection: out[m][a*256+hh] = v[m][a] . Uo[a][:,hh] + bo[a][hh] ----
    #pragma unroll 1
    for (int i = 0; i < 4; i++) {
        int q  = tid + i * THREADS;            // 0..1023
        int a  = q >> 8, hh = q & 255;
        float uo[16];
        #pragma unroll
        for (int r = 0; r < 16; r++) uo[r] = __ldg(Uo + (size_t)a * 4096 + r * 256 + hh);
        float bov = __ldg(bo + a * 256 + hh);
        #pragma unroll 4
        for (int m = 0; m < 64; m++) {
            const float4* vr4 = (const float4*)(sX + (m * 4 + a) * 16);
            float4 v0 = vr4[0], v1 = vr4[1], v2 = vr4[2], v3 = vr4[3];
            float sacc = bov;
            sacc += v0.x * uo[0]  + v0.y * uo[1]  + v0.z * uo[2]  + v0.w * uo[3];
            sacc += v1.x * uo[4]  + v1.y * uo[5]  + v1.z * uo[6]  + v1.w * uo[7];
            sacc += v2.x * uo[8]  + v2.y * uo[9]  + v2.z * uo[10] + v2.w * uo[11];
            sacc += v3.x * uo[12] + v3.y * uo[13] + v3.z * uo[14] + v3.w * uo[15];
            out[(size_t)(b0 + m) * 1024 + q] = sacc;
        }
    }
}

extern "C" void kernel_launch(void* const* d_in, const int* in_sizes, int n_in,
                              void* d_out, int out_size) {
    const float* nh = (const float*)d_in[0];
    const float* te = (const float*)d_in[1];
    const float* U  = (const float*)d_in[2];
    const float* bB = (const float*)d_in[3];
    const float* Ut = (const float*)d_in[4];
    const float* bt = (const float*)d_in[5];
    const float* Uo = (const float*)d_in[6];
    const float* bo = (const float*)d_in[7];
    float* out = (float*)d_out;

    const int smem_bytes = (16384 + 8192 + 4096) * (int)sizeof(float); // 112 KB
    cudaFuncSetAttribute(tt_fused_kernel,
                         cudaFuncAttributeMaxDynamicSharedMemorySize, smem_bytes);
    tt_fused_kernel<<<256, THREADS, smem_bytes>>>(nh, te, U, bB, Ut, bt, Uo, bo, out);
}